// round 3
// baseline (speedup 1.0000x reference)
#include <cuda_runtime.h>

#define NCLS 32
#define SOSC 30
#define EOSC 31
#define LOG2E 1.4426950408889634f
#define LN2F  0.6931471805599453f

typedef unsigned long long u64;

__device__ __forceinline__ float ex2f(float x){ float r; asm("ex2.approx.f32 %0, %1;" : "=f"(r) : "f"(x)); return r; }
__device__ __forceinline__ float lg2f_(float x){ float r; asm("lg2.approx.f32 %0, %1;" : "=f"(r) : "f"(x)); return r; }
__device__ __forceinline__ float rcpf(float x){ float r; asm("rcp.approx.f32 %0, %1;" : "=f"(r) : "f"(x)); return r; }
__device__ __forceinline__ u64 pk2(float lo, float hi){ u64 r; asm("mov.b64 %0, {%1,%2};" : "=l"(r) : "f"(lo), "f"(hi)); return r; }
__device__ __forceinline__ void up2(u64 v, float& lo, float& hi){ asm("mov.b64 {%0,%1}, %2;" : "=f"(lo), "=f"(hi) : "l"(v)); }
__device__ __forceinline__ u64 ffma2(u64 a, u64 b, u64 c){ u64 d; asm("fma.rn.f32x2 %0, %1, %2, %3;" : "=l"(d) : "l"(a), "l"(b), "l"(c)); return d; }
__device__ __forceinline__ u64 fadd2(u64 a, u64 b){ u64 d; asm("add.rn.f32x2 %0, %1, %2;" : "=l"(d) : "l"(a), "l"(b)); return d; }
__device__ __forceinline__ u64 fmul2(u64 a, u64 b){ u64 d; asm("mul.rn.f32x2 %0, %1, %2;" : "=l"(d) : "l"(a), "l"(b)); return d; }
__device__ __forceinline__ u64 fsub2(u64 a, u64 b){ u64 d; asm("sub.rn.f32x2 %0, %1, %2;" : "=l"(d) : "l"(a), "l"(b)); return d; }

// Exp-domain CRF forward. 1 warp = 2 batches (f32x2), lane = class.
// Fast path (verified all-ones mask): branch-free, no blend, stale rescale.
// Slow path: fully general masked recurrence (rarely taken).
__global__ __launch_bounds__(256)
void crf_fwd(const float* __restrict__ feats,
             const float* __restrict__ mask,
             const float* __restrict__ trans,
             float* __restrict__ out,
             int seq, int batch)
{
    __shared__ __align__(16) u64 pbuf[8][2][NCLS];
    const int lane = threadIdx.x & 31;
    const int wl   = threadIdx.x >> 5;
    const int pair = blockIdx.x * 8 + wl;
    const int npairs = (batch + 1) >> 1;
    if (pair >= npairs) return;
    const int b0 = pair * 2;
    int b1 = b0 + 1;
    const bool has_b1 = (b1 < batch);
    if (!has_b1) b1 = b0;

    // E[c,k] = exp(T[c,k]) duplicated into both halves. NEG rows -> exact 0.
    u64 E2[NCLS];
#pragma unroll
    for (int k = 0; k < NCLS; ++k){
        float e = ex2f(trans[lane * NCLS + k] * LOG2E);
        E2[k] = pk2(e, e);
    }
    const float ee = ex2f(trans[EOSC * NCLS + lane] * LOG2E);  // exp(T[EOS,lane])

    float pinit = (lane == SOSC) ? 1.0f : 0.0f;
    u64 P2 = pk2(pinit, pinit);
    float C0 = 0.0f, C1 = 0.0f;     // log2-domain running offsets

    const size_t fstride = (size_t)batch * NCLS;
    const float* fpA = feats + (size_t)b0 * NCLS + lane;
    const float* fpB = feats + (size_t)b1 * NCLS + lane;
    const float* mpA = mask + b0;
    const float* mpB = mask + b1;

    // ---- pre-scan: is this warp's mask all ones? ----
    bool ok = true;
    for (int tm = lane; tm < seq; tm += 32){
        ok = ok && (mpA[(size_t)tm * batch] == 1.0f)
                && (mpB[(size_t)tm * batch] == 1.0f);
    }
    const bool allones = __all_sync(0xffffffffu, ok);

    if (allones){
        // ---------------- FAST PATH: mask == 1 everywhere ----------------
        u64 fexp2[8];
#pragma unroll
        for (int j = 0; j < 8; ++j){
            int tc = (j < seq) ? j : (seq - 1);
            fexp2[j] = pk2(ex2f(fpA[(size_t)tc * fstride] * LOG2E),
                           ex2f(fpB[(size_t)tc * fstride] * LOG2E));
        }
        int t = 0;
        for (int t0 = 0; t0 + 8 <= seq; t0 += 8){
#pragma unroll
            for (int j = 0; j < 8; ++j){
                // stale rescale pivot: from PRE-step P, runs parallel to matvec
                float r0 = 1.0f, r1 = 1.0f;
                if ((j & 3) == 0){
                    float p0, p1; up2(P2, p0, p1);
                    float d0 = __shfl_sync(0xffffffffu, p0, 0);
                    float d1 = __shfl_sync(0xffffffffu, p1, 0);
                    r0 = (d0 > 1e-30f) ? rcpf(d0) : 1.0f;
                    r1 = (d1 > 1e-30f) ? rcpf(d1) : 1.0f;
                }
                pbuf[wl][j & 1][lane] = P2;
                __syncwarp();
                const u64* pb = pbuf[wl][j & 1];
                u64 a0 = 0ull, a1 = 0ull, a2 = 0ull, a3 = 0ull;
#pragma unroll
                for (int k = 0; k < NCLS; k += 8){
                    ulonglong2 q0 = *reinterpret_cast<const ulonglong2*>(&pb[k]);
                    ulonglong2 q1 = *reinterpret_cast<const ulonglong2*>(&pb[k+2]);
                    ulonglong2 q2 = *reinterpret_cast<const ulonglong2*>(&pb[k+4]);
                    ulonglong2 q3 = *reinterpret_cast<const ulonglong2*>(&pb[k+6]);
                    a0 = ffma2(E2[k],   q0.x, a0);
                    a1 = ffma2(E2[k+1], q0.y, a1);
                    a2 = ffma2(E2[k+2], q1.x, a2);
                    a3 = ffma2(E2[k+3], q1.y, a3);
                    a0 = ffma2(E2[k+4], q2.x, a0);
                    a1 = ffma2(E2[k+5], q2.y, a1);
                    a2 = ffma2(E2[k+6], q3.x, a2);
                    a3 = ffma2(E2[k+7], q3.y, a3);
                }
                u64 s2 = fadd2(fadd2(a0, a1), fadd2(a2, a3));
                u64 Pn = fmul2(s2, fexp2[j]);
                if ((j & 3) == 0){
                    Pn = fmul2(Pn, pk2(r0, r1));   // only this lands on the path
                    C0 -= lg2f_(r0);                // side chain
                    C1 -= lg2f_(r1);
                }
                P2 = Pn;
                int tn = t0 + 8 + j;
                int tc = (tn < seq) ? tn : (seq - 1);
                fexp2[j] = pk2(ex2f(fpA[(size_t)tc * fstride] * LOG2E),
                               ex2f(fpB[(size_t)tc * fstride] * LOG2E));
            }
        }
        t = (seq & ~7);
        for (; t < seq; ++t){   // tail (not hit for seq=512)
            pbuf[wl][t & 1][lane] = P2;
            __syncwarp();
            const u64* pb = pbuf[wl][t & 1];
            u64 a0 = 0ull, a1 = 0ull;
#pragma unroll
            for (int k = 0; k < NCLS; k += 4){
                ulonglong2 q0 = *reinterpret_cast<const ulonglong2*>(&pb[k]);
                ulonglong2 q1 = *reinterpret_cast<const ulonglong2*>(&pb[k+2]);
                a0 = ffma2(E2[k],   q0.x, a0);
                a1 = ffma2(E2[k+1], q0.y, a1);
                a0 = ffma2(E2[k+2], q1.x, a0);
                a1 = ffma2(E2[k+3], q1.y, a1);
            }
            u64 s2 = fadd2(a0, a1);
            float fa = fpA[(size_t)t * fstride];
            float fb = fpB[(size_t)t * fstride];
            u64 Pn = fmul2(s2, pk2(ex2f(fa * LOG2E), ex2f(fb * LOG2E)));
            float p0, p1; up2(Pn, p0, p1);
            float d0 = __shfl_sync(0xffffffffu, p0, 0);
            float d1 = __shfl_sync(0xffffffffu, p1, 0);
            float r0 = (d0 > 1e-30f) ? rcpf(d0) : 1.0f;
            float r1 = (d1 > 1e-30f) ? rcpf(d1) : 1.0f;
            P2 = fmul2(Pn, pk2(r0, r1));
            C0 -= lg2f_(r0);
            C1 -= lg2f_(r1);
        }
    } else {
        // ---------------- SLOW PATH: general mask ----------------
        for (int t = 0; t < seq; ++t){
            pbuf[wl][t & 1][lane] = P2;
            __syncwarp();
            const u64* pb = pbuf[wl][t & 1];
            u64 a0 = 0ull, a1 = 0ull, a2 = 0ull, a3 = 0ull;
#pragma unroll
            for (int k = 0; k < NCLS; k += 4){
                ulonglong2 q0 = *reinterpret_cast<const ulonglong2*>(&pb[k]);
                ulonglong2 q1 = *reinterpret_cast<const ulonglong2*>(&pb[k+2]);
                a0 = ffma2(E2[k],   q0.x, a0);
                a1 = ffma2(E2[k+1], q0.y, a1);
                a2 = ffma2(E2[k+2], q1.x, a2);
                a3 = ffma2(E2[k+3], q1.y, a3);
            }
            u64 s2 = fadd2(fadd2(a0, a1), fadd2(a2, a3));
            float fa = fpA[(size_t)t * fstride];
            float fb = fpB[(size_t)t * fstride];
            u64 Pn = fmul2(s2, pk2(ex2f(fa * LOG2E), ex2f(fb * LOG2E)));
            float mk0 = mpA[(size_t)t * batch];
            float mk1 = mpB[(size_t)t * batch];
            u64 Pold = P2;
            P2 = ffma2(pk2(mk0, mk1), fsub2(Pn, P2), P2);
            if (mk0 * (1.0f - mk0) != 0.0f || mk1 * (1.0f - mk1) != 0.0f){
                // fractional mask: exact log-domain blend
                float po0, po1, pn0, pn1;
                up2(Pold, po0, po1); up2(Pn, pn0, pn1);
                float r0 = ex2f(mk0 * lg2f_(pn0) + (1.0f - mk0) * lg2f_(po0));
                float r1 = ex2f(mk1 * lg2f_(pn1) + (1.0f - mk1) * lg2f_(po1));
                P2 = pk2(r0, r1);
            }
            {   // rescale every step (slow path: robustness over speed)
                float p0, p1; up2(P2, p0, p1);
                float d0 = __shfl_sync(0xffffffffu, p0, 0);
                float d1 = __shfl_sync(0xffffffffu, p1, 0);
                float r0 = (d0 > 1e-30f) ? rcpf(d0) : 1.0f;
                float r1 = (d1 > 1e-30f) ? rcpf(d1) : 1.0f;
                P2 = fmul2(P2, pk2(r0, r1));
                C0 -= lg2f_(r0);
                C1 -= lg2f_(r1);
            }
        }
    }

    // Epilogue: out[b] = ln2 * (C + log2( sum_c P[c] * exp(T[EOS,c]) ))
    float p0, p1; up2(P2, p0, p1);
    float v0 = p0 * ee;
    float v1 = p1 * ee;
#pragma unroll
    for (int off = 16; off > 0; off >>= 1){
        v0 += __shfl_xor_sync(0xffffffffu, v0, off);
        v1 += __shfl_xor_sync(0xffffffffu, v1, off);
    }
    if (lane == 0){
        out[b0] = (C0 + lg2f_(v0)) * LN2F;
        if (has_b1) out[b1] = (C1 + lg2f_(v1)) * LN2F;
    }
}

extern "C" void kernel_launch(void* const* d_in, const int* in_sizes, int n_in,
                              void* d_out, int out_size)
{
    const float* feats = (const float*)d_in[0];
    const float* mask  = (const float*)d_in[1];
    const float* trans = (const float*)d_in[2];
    float* out = (float*)d_out;

    const int batch = out_size;                 // out is (batch,)
    const int seq   = in_sizes[1] / batch;      // mask is (seq, batch)

    const int npairs = (batch + 1) >> 1;        // 2 batches per warp
    const int warps_per_cta = 8;                // 256 threads -> 128 CTAs
    const int blocks = (npairs + warps_per_cta - 1) / warps_per_cta;

    crf_fwd<<<blocks, warps_per_cta * 32>>>(feats, mask, trans, out, seq, batch);
}

// round 6
// speedup vs baseline: 1.0919x; 1.0919x over previous
#include <cuda_runtime.h>

#define NCLS 32
#define SOSC 30
#define EOSC 31
#define LOG2E 1.4426950408889634f
#define LN2F  0.6931471805599453f

typedef unsigned long long u64;

__device__ __forceinline__ float ex2f(float x){ float r; asm("ex2.approx.f32 %0, %1;" : "=f"(r) : "f"(x)); return r; }
__device__ __forceinline__ float lg2f_(float x){ float r; asm("lg2.approx.f32 %0, %1;" : "=f"(r) : "f"(x)); return r; }
__device__ __forceinline__ u64 pk2(float lo, float hi){ u64 r; asm("mov.b64 %0, {%1,%2};" : "=l"(r) : "f"(lo), "f"(hi)); return r; }
__device__ __forceinline__ void up2(u64 v, float& lo, float& hi){ asm("mov.b64 {%0,%1}, %2;" : "=f"(lo), "=f"(hi) : "l"(v)); }
__device__ __forceinline__ u64 ffma2(u64 a, u64 b, u64 c){ u64 d; asm("fma.rn.f32x2 %0, %1, %2, %3;" : "=l"(d) : "l"(a), "l"(b), "l"(c)); return d; }
__device__ __forceinline__ u64 fadd2(u64 a, u64 b){ u64 d; asm("add.rn.f32x2 %0, %1, %2;" : "=l"(d) : "l"(a), "l"(b)); return d; }
__device__ __forceinline__ u64 fmul2(u64 a, u64 b){ u64 d; asm("mul.rn.f32x2 %0, %1, %2;" : "=l"(d) : "l"(a), "l"(b)); return d; }
__device__ __forceinline__ u64 fsub2(u64 a, u64 b){ u64 d; asm("sub.rn.f32x2 %0, %1, %2;" : "=l"(d) : "l"(a), "l"(b)); return d; }

// Exact power-of-2 rescale factor from a stale probe value d (pure ALU):
// returns r = 2^(127 - e), e = biased exponent of d, and accumulates the true
// exponent into eacc, so d*r lands in ~[1,2). Returns 1.0f (no-op) for
// zero/denormal (e==0), for e==254 (r would be denormal 2^-127), and inf/nan.
__device__ __forceinline__ float po2_rescale(float d, int& eacc){
    unsigned u = __float_as_uint(d);
    int e = (int)(u >> 23) & 0xff;
    if (e == 0 || e >= 254) return 1.0f;
    eacc += (e - 127);
    return __uint_as_float((unsigned)(254 - e) << 23);
}

// Exp-domain CRF forward. 1 CTA = 1 warp = 2 batches (f32x2), lane = class.
// P_{t+1}[c] = fexp_t[c] * sum_k E[c,k] * P_t[k], mask applied as exp-domain
// linear blend (exact for mask in {0,1}). Every 4 steps the WHOLE state
// (post-blend, so both blend operands share one scale) is rescaled by an
// exact power of two derived from the stale pre-step P via ALU bit ops.
__global__ __launch_bounds__(32, 8)
void crf_fwd(const float* __restrict__ feats,
             const float* __restrict__ mask,
             const float* __restrict__ trans,
             float* __restrict__ out,
             int seq, int batch)
{
    __shared__ __align__(16) u64 pbuf[2][NCLS];
    const int lane = threadIdx.x & 31;
    const int pair = blockIdx.x;
    const int b0 = pair * 2;
    int b1 = b0 + 1;
    const bool has_b1 = (b1 < batch);
    if (!has_b1) b1 = b0;

    // E[c,k] = exp(T[c,k]) duplicated into both halves. NEG rows -> exact 0.
    u64 E2[NCLS];
#pragma unroll
    for (int k = 0; k < NCLS; ++k){
        float e = ex2f(trans[lane * NCLS + k] * LOG2E);
        E2[k] = pk2(e, e);
    }
    const float ee = ex2f(trans[EOSC * NCLS + lane] * LOG2E);  // exp(T[EOS,lane])

    float pinit = (lane == SOSC) ? 1.0f : 0.0f;
    u64 P2 = pk2(pinit, pinit);
    int   eC0 = 0, eC1 = 0;        // exact integer log2 offsets

    const float* fbaseA = feats + (size_t)b0 * NCLS + lane;
    const float* fbaseB = feats + (size_t)b1 * NCLS + lane;
    const float* mbase  = mask  + b0;
    const unsigned fstep = (unsigned)batch * NCLS;
    const unsigned mstep = (unsigned)batch;
    const unsigned flast = (unsigned)(seq - 1) * fstep;  // last VALID offsets
    const unsigned mlast = (unsigned)(seq - 1) * mstep;

    // 8-deep prefetch: fexp = exp(feat), computed off the critical path.
    u64 fexp2[8], m2[8];
#pragma unroll
    for (int j = 0; j < 8; ++j){
        unsigned fc = (j < seq) ? (unsigned)j * fstep : flast;
        unsigned mc = (j < seq) ? (unsigned)j * mstep : mlast;
        fexp2[j] = pk2(ex2f(fbaseA[fc] * LOG2E), ex2f(fbaseB[fc] * LOG2E));
        float ma = mbase[mc];
        float mb = has_b1 ? mbase[mc + 1] : ma;
        m2[j] = pk2(ma, mb);
    }

    unsigned foff = 8u * fstep;   // running offsets for prefetch (t+8)
    unsigned moff = 8u * mstep;

    for (int t0 = 0; t0 + 8 <= seq; t0 += 8){
#pragma unroll
        for (int j = 0; j < 8; ++j){
            // stale rescale pivot from PRE-step P: ALU+shfl, overlaps matvec
            float r0 = 1.0f, r1 = 1.0f;
            if ((j & 3) == 0){
                float p0, p1; up2(P2, p0, p1);
                float d0 = __shfl_sync(0xffffffffu, p0, 0);
                float d1 = __shfl_sync(0xffffffffu, p1, 0);
                r0 = po2_rescale(d0, eC0);
                r1 = po2_rescale(d1, eC1);
            }
            pbuf[j & 1][lane] = P2;            // broadcast P to warp
            __syncwarp();
            const u64* pb = pbuf[j & 1];
            u64 a0 = 0ull, a1 = 0ull, a2 = 0ull, a3 = 0ull;
#pragma unroll
            for (int k = 0; k < NCLS; k += 8){
                ulonglong2 q0 = *reinterpret_cast<const ulonglong2*>(&pb[k]);
                ulonglong2 q1 = *reinterpret_cast<const ulonglong2*>(&pb[k+2]);
                ulonglong2 q2 = *reinterpret_cast<const ulonglong2*>(&pb[k+4]);
                ulonglong2 q3 = *reinterpret_cast<const ulonglong2*>(&pb[k+6]);
                a0 = ffma2(E2[k],   q0.x, a0);
                a1 = ffma2(E2[k+1], q0.y, a1);
                a2 = ffma2(E2[k+2], q1.x, a2);
                a3 = ffma2(E2[k+3], q1.y, a3);
                a0 = ffma2(E2[k+4], q2.x, a0);
                a1 = ffma2(E2[k+5], q2.y, a1);
                a2 = ffma2(E2[k+6], q3.x, a2);
                a3 = ffma2(E2[k+7], q3.y, a3);
            }
            u64 s2 = fadd2(fadd2(a0, a1), fadd2(a2, a3));
            u64 Pn = fmul2(s2, fexp2[j]);
            // blend FIRST (both operands at the same scale; exact for m in {0,1})
            P2 = ffma2(m2[j], fsub2(Pn, P2), P2);
            // THEN rescale the whole blended state (uniform scale change)
            if ((j & 3) == 0)
                P2 = fmul2(P2, pk2(r0, r1));
            // prefetch step t0+8+j, offsets CLAMPED to last valid step
            {
                int tn = t0 + 8 + j;
                unsigned fc = (tn < seq) ? foff : flast;
                unsigned mc = (tn < seq) ? moff : mlast;
                fexp2[j] = pk2(ex2f(fbaseA[fc] * LOG2E), ex2f(fbaseB[fc] * LOG2E));
                float ma = mbase[mc];
                float mb = has_b1 ? mbase[mc + 1] : ma;
                m2[j] = pk2(ma, mb);
                foff += fstep; moff += mstep;
            }
        }
    }
    // tail (seq % 8 != 0; not hit for seq=512)
    for (int t = (seq & ~7); t < seq; ++t){
        pbuf[t & 1][lane] = P2;
        __syncwarp();
        const u64* pb = pbuf[t & 1];
        u64 a0 = 0ull, a1 = 0ull;
#pragma unroll
        for (int k = 0; k < NCLS; k += 4){
            ulonglong2 q0 = *reinterpret_cast<const ulonglong2*>(&pb[k]);
            ulonglong2 q1 = *reinterpret_cast<const ulonglong2*>(&pb[k+2]);
            a0 = ffma2(E2[k],   q0.x, a0);
            a1 = ffma2(E2[k+1], q0.y, a1);
            a0 = ffma2(E2[k+2], q1.x, a0);
            a1 = ffma2(E2[k+3], q1.y, a1);
        }
        u64 s2 = fadd2(a0, a1);
        unsigned fc = (unsigned)t * fstep;
        unsigned mc = (unsigned)t * mstep;
        u64 Pn = fmul2(s2, pk2(ex2f(fbaseA[fc] * LOG2E), ex2f(fbaseB[fc] * LOG2E)));
        float ma = mbase[mc];
        float mb = has_b1 ? mbase[mc + 1] : ma;
        P2 = ffma2(pk2(ma, mb), fsub2(Pn, P2), P2);   // blend first
        {   // then rescale blended state
            float p0, p1; up2(P2, p0, p1);
            float d0 = __shfl_sync(0xffffffffu, p0, 0);
            float d1 = __shfl_sync(0xffffffffu, p1, 0);
            float r0 = po2_rescale(d0, eC0);
            float r1 = po2_rescale(d1, eC1);
            P2 = fmul2(P2, pk2(r0, r1));
        }
    }

    // Epilogue: out[b] = ln2 * (eC + log2( sum_c P[c] * exp(T[EOS,c]) ))
    float p0, p1; up2(P2, p0, p1);
    float v0 = p0 * ee;
    float v1 = p1 * ee;
#pragma unroll
    for (int off = 16; off > 0; off >>= 1){
        v0 += __shfl_xor_sync(0xffffffffu, v0, off);
        v1 += __shfl_xor_sync(0xffffffffu, v1, off);
    }
    if (lane == 0){
        out[b0] = ((float)eC0 + lg2f_(v0)) * LN2F;
        if (has_b1) out[b1] = ((float)eC1 + lg2f_(v1)) * LN2F;
    }
}

extern "C" void kernel_launch(void* const* d_in, const int* in_sizes, int n_in,
                              void* d_out, int out_size)
{
    const float* feats = (const float*)d_in[0];
    const float* mask  = (const float*)d_in[1];
    const float* trans = (const float*)d_in[2];
    float* out = (float*)d_out;

    const int batch = out_size;                 // out is (batch,)
    const int seq   = in_sizes[1] / batch;      // mask is (seq, batch)

    const int npairs = (batch + 1) >> 1;        // 2 batches per warp
    // 1 warp per CTA: npairs CTAs spread over all 148 SMs (balanced)
    crf_fwd<<<npairs, 32>>>(feats, mask, trans, out, seq, batch);
}

// round 7
// speedup vs baseline: 1.2341x; 1.1302x over previous
#include <cuda_runtime.h>

#define NCLS 32
#define SOSC 30
#define EOSC 31
#define LOG2E 1.4426950408889634f
#define LN2F  0.6931471805599453f

typedef unsigned long long u64;

__device__ __forceinline__ float ex2f(float x){ float r; asm("ex2.approx.f32 %0, %1;" : "=f"(r) : "f"(x)); return r; }
__device__ __forceinline__ float lg2f_(float x){ float r; asm("lg2.approx.f32 %0, %1;" : "=f"(r) : "f"(x)); return r; }
__device__ __forceinline__ u64 pk2(float lo, float hi){ u64 r; asm("mov.b64 %0, {%1,%2};" : "=l"(r) : "f"(lo), "f"(hi)); return r; }
__device__ __forceinline__ void up2(u64 v, float& lo, float& hi){ asm("mov.b64 {%0,%1}, %2;" : "=f"(lo), "=f"(hi) : "l"(v)); }
__device__ __forceinline__ u64 ffma2(u64 a, u64 b, u64 c){ u64 d; asm("fma.rn.f32x2 %0, %1, %2, %3;" : "=l"(d) : "l"(a), "l"(b), "l"(c)); return d; }
__device__ __forceinline__ u64 fadd2(u64 a, u64 b){ u64 d; asm("add.rn.f32x2 %0, %1, %2;" : "=l"(d) : "l"(a), "l"(b)); return d; }
__device__ __forceinline__ u64 fmul2(u64 a, u64 b){ u64 d; asm("mul.rn.f32x2 %0, %1, %2;" : "=l"(d) : "l"(a), "l"(b)); return d; }
__device__ __forceinline__ u64 fsub2(u64 a, u64 b){ u64 d; asm("sub.rn.f32x2 %0, %1, %2;" : "=l"(d) : "l"(a), "l"(b)); return d; }

// Exact power-of-2 rescale factor from a stale probe value d (pure ALU).
__device__ __forceinline__ float po2_rescale(float d, int& eacc){
    unsigned u = __float_as_uint(d);
    int e = (int)(u >> 23) & 0xff;
    if (e == 0 || e >= 254) return 1.0f;
    eacc += (e - 127);
    return __uint_as_float((unsigned)(254 - e) << 23);
}

// Exp-domain CRF forward, LSU-minimal decomposition:
// warp = 4 batches, 8 lanes per batch, each lane owns 4 classes (full k-dot).
// Per step per warp: 8 LDS.128 + 1 STS.128 + 1 LDG.128 + 1 LDG.32 (11 LSU ops
// for 4 batches vs 8/batch in the broadcast layout). K-pairs arrive packed
// from LDS.128 and feed fma.rn.f32x2 directly. Blend-then-po2-rescale (every
// 4 steps, stale pivot) as in the round-6 passing scheme.
__global__ __launch_bounds__(64, 4)
void crf_fwd(const float* __restrict__ feats,
             const float* __restrict__ mask,
             const float* __restrict__ trans,
             float* __restrict__ out,
             int seq, int batch)
{
    // [warp][dbl][batch][36]: 36-float (144B) batch stride -> conflict-free loads
    __shared__ __align__(16) float pbuf[2][2][4][36];
    const int tid  = threadIdx.x;
    const int wid  = tid >> 5;
    const int lane = tid & 31;
    const int b    = lane >> 3;      // batch slot in warp (0..3)
    const int g    = lane & 7;       // lane group index -> classes 4g..4g+3
    const int wg   = blockIdx.x * 2 + wid;
    const int batch0 = wg * 4;
    if (batch0 >= batch) return;
    int bb = batch0 + b;
    const bool real = (bb < batch);
    if (!real) bb = batch - 1;       // duplicate compute, skip store
    const int c0 = g * 4;

    // E2[ci][kp] = (exp(T[c0+ci][2kp]), exp(T[c0+ci][2kp+1]))  (64 u64)
    u64 E2[4][16];
#pragma unroll
    for (int ci = 0; ci < 4; ++ci){
        const float* tr = trans + (c0 + ci) * NCLS;
#pragma unroll
        for (int kp = 0; kp < 16; ++kp){
            E2[ci][kp] = pk2(ex2f(tr[2*kp] * LOG2E), ex2f(tr[2*kp+1] * LOG2E));
        }
    }
    u64 ee2[2];
    {
        const float* te = trans + EOSC * NCLS + c0;
        ee2[0] = pk2(ex2f(te[0]*LOG2E), ex2f(te[1]*LOG2E));
        ee2[1] = pk2(ex2f(te[2]*LOG2E), ex2f(te[3]*LOG2E));
    }

    // State: P for this lane's 4 classes, packed as 2 f32x2.
    u64 P2[2];
    {
        float i0 = (c0+0==SOSC)?1.f:0.f, i1 = (c0+1==SOSC)?1.f:0.f;
        float i2 = (c0+2==SOSC)?1.f:0.f, i3 = (c0+3==SOSC)?1.f:0.f;
        P2[0] = pk2(i0, i1); P2[1] = pk2(i2, i3);
    }
    int eC = 0;   // exact integer log2 offset (same across the 8-lane group)

    const float* fbase = feats + (size_t)bb * NCLS + c0;
    const float* mbase = mask + bb;
    const unsigned fstep = (unsigned)batch * NCLS;
    const unsigned mstep = (unsigned)batch;

    // 4-deep prefetch: fexp = exp(feat) for this lane's 4 classes + mask
    u64 fe[4][2]; float mk[4];
#pragma unroll
    for (int j = 0; j < 4; ++j){
        int tc = (j < seq) ? j : (seq - 1);
        float4 f4 = *reinterpret_cast<const float4*>(fbase + (size_t)((unsigned)tc * fstep));
        fe[j][0] = pk2(ex2f(f4.x*LOG2E), ex2f(f4.y*LOG2E));
        fe[j][1] = pk2(ex2f(f4.z*LOG2E), ex2f(f4.w*LOG2E));
        mk[j] = mbase[(unsigned)tc * mstep];
    }

    float* const stbase = &pbuf[wid][0][b][c0];
    const float* const ldbase = &pbuf[wid][0][b][0];
    const int dstride = 4 * 36;      // floats between the two dbl buffers

    int t0 = 0;
    for (; t0 + 4 <= seq; t0 += 4){
#pragma unroll
        for (int j = 0; j < 4; ++j){
            // stale rescale pivot (pre-step P[class 0] of this batch group)
            float r = 1.0f;
            if (j == 0){
                float plo, phi; up2(P2[0], plo, phi);
                float piv = __shfl_sync(0xffffffffu, plo, lane & 24);
                r = po2_rescale(piv, eC);
            }
            // publish this lane's 4 P values (16B) to the group buffer
            {
                ulonglong2 v; v.x = P2[0]; v.y = P2[1];
                *reinterpret_cast<ulonglong2*>(stbase + (j & 1) * dstride) = v;
            }
            __syncwarp();
            const float* ld = ldbase + (j & 1) * dstride;
            u64 q[8][2];
#pragma unroll
            for (int s = 0; s < 8; ++s){
                ulonglong2 v = *reinterpret_cast<const ulonglong2*>(ld + s * 4);
                q[s][0] = v.x; q[s][1] = v.y;
            }
            u64 acc[4][2];
#pragma unroll
            for (int ci = 0; ci < 4; ++ci){ acc[ci][0] = 0ull; acc[ci][1] = 0ull; }
#pragma unroll
            for (int s = 0; s < 8; ++s){
#pragma unroll
                for (int ci = 0; ci < 4; ++ci){
                    acc[ci][0] = ffma2(E2[ci][2*s],   q[s][0], acc[ci][0]);
                    acc[ci][1] = ffma2(E2[ci][2*s+1], q[s][1], acc[ci][1]);
                }
            }
            float sv[4];
#pragma unroll
            for (int ci = 0; ci < 4; ++ci){
                u64 a = fadd2(acc[ci][0], acc[ci][1]);
                float lo, hi; up2(a, lo, hi);
                sv[ci] = lo + hi;               // horizontal k-sum
            }
            u64 Pn0 = fmul2(pk2(sv[0], sv[1]), fe[j][0]);
            u64 Pn1 = fmul2(pk2(sv[2], sv[3]), fe[j][1]);
            // blend first (operands share one scale; exact for mask in {0,1})
            u64 mm = pk2(mk[j], mk[j]);
            P2[0] = ffma2(mm, fsub2(Pn0, P2[0]), P2[0]);
            P2[1] = ffma2(mm, fsub2(Pn1, P2[1]), P2[1]);
            // then uniform po2 rescale of the blended state
            if (j == 0){
                u64 rr = pk2(r, r);
                P2[0] = fmul2(P2[0], rr);
                P2[1] = fmul2(P2[1], rr);
            }
            // prefetch step t0+4+j (index clamped BEFORE offset computation)
            {
                int tn = t0 + 4 + j;
                int tc = (tn < seq) ? tn : (seq - 1);
                float4 f4 = *reinterpret_cast<const float4*>(fbase + (size_t)((unsigned)tc * fstep));
                fe[j][0] = pk2(ex2f(f4.x*LOG2E), ex2f(f4.y*LOG2E));
                fe[j][1] = pk2(ex2f(f4.z*LOG2E), ex2f(f4.w*LOG2E));
                mk[j] = mbase[(unsigned)tc * mstep];
            }
        }
    }
    // tail (seq % 4 != 0; not hit for seq=512)
    for (int t = t0; t < seq; ++t){
        {
            ulonglong2 v; v.x = P2[0]; v.y = P2[1];
            *reinterpret_cast<ulonglong2*>(stbase + (t & 1) * dstride) = v;
        }
        __syncwarp();
        const float* ld = ldbase + (t & 1) * dstride;
        u64 acc0 = 0ull, acc1 = 0ull, acc2a = 0ull, acc3 = 0ull;
        float sv[4];
#pragma unroll
        for (int ci = 0; ci < 4; ++ci){
            u64 a0 = 0ull, a1 = 0ull;
#pragma unroll
            for (int s = 0; s < 8; ++s){
                ulonglong2 v = *reinterpret_cast<const ulonglong2*>(ld + s * 4);
                a0 = ffma2(E2[ci][2*s],   v.x, a0);
                a1 = ffma2(E2[ci][2*s+1], v.y, a1);
            }
            u64 a = fadd2(a0, a1);
            float lo, hi; up2(a, lo, hi);
            sv[ci] = lo + hi;
        }
        (void)acc0; (void)acc1; (void)acc2a; (void)acc3;
        float4 f4 = *reinterpret_cast<const float4*>(fbase + (size_t)((unsigned)t * fstep));
        u64 Pn0 = fmul2(pk2(sv[0], sv[1]), pk2(ex2f(f4.x*LOG2E), ex2f(f4.y*LOG2E)));
        u64 Pn1 = fmul2(pk2(sv[2], sv[3]), pk2(ex2f(f4.z*LOG2E), ex2f(f4.w*LOG2E)));
        float m = mbase[(unsigned)t * mstep];
        u64 mm = pk2(m, m);
        P2[0] = ffma2(mm, fsub2(Pn0, P2[0]), P2[0]);
        P2[1] = ffma2(mm, fsub2(Pn1, P2[1]), P2[1]);
        {   // rescale every tail step
            float plo, phi; up2(P2[0], plo, phi);
            float piv = __shfl_sync(0xffffffffu, plo, lane & 24);
            float r = po2_rescale(piv, eC);
            u64 rr = pk2(r, r);
            P2[0] = fmul2(P2[0], rr);
            P2[1] = fmul2(P2[1], rr);
        }
    }

    // Epilogue: out[b] = ln2 * (eC + log2( sum_c P[c] * exp(T[EOS,c]) ))
    u64 w2 = fmul2(P2[0], ee2[0]);
    w2 = ffma2(P2[1], ee2[1], w2);
    float lo, hi; up2(w2, lo, hi);
    float v = lo + hi;
    v += __shfl_xor_sync(0xffffffffu, v, 1);   // reduce within 8-lane group
    v += __shfl_xor_sync(0xffffffffu, v, 2);
    v += __shfl_xor_sync(0xffffffffu, v, 4);
    if (g == 0 && real)
        out[bb] = ((float)eC + lg2f_(v)) * LN2F;
}

extern "C" void kernel_launch(void* const* d_in, const int* in_sizes, int n_in,
                              void* d_out, int out_size)
{
    const float* feats = (const float*)d_in[0];
    const float* mask  = (const float*)d_in[1];
    const float* trans = (const float*)d_in[2];
    float* out = (float*)d_out;

    const int batch = out_size;                 // out is (batch,)
    const int seq   = in_sizes[1] / batch;      // mask is (seq, batch)

    const int nwarps = (batch + 3) / 4;         // 4 batches per warp
    const int blocks = (nwarps + 1) / 2;        // 2 warps per CTA
    crf_fwd<<<blocks, 64>>>(feats, mask, trans, out, seq, batch);
}

// round 8
// speedup vs baseline: 1.6239x; 1.3159x over previous
#include <cuda_runtime.h>

#define NCLS 32
#define SOSC 30
#define EOSC 31
#define LOG2E 1.4426950408889634f
#define LN2F  0.6931471805599453f

typedef unsigned long long u64;

__device__ __forceinline__ float ex2f(float x){ float r; asm("ex2.approx.f32 %0, %1;" : "=f"(r) : "f"(x)); return r; }
__device__ __forceinline__ float lg2f_(float x){ float r; asm("lg2.approx.f32 %0, %1;" : "=f"(r) : "f"(x)); return r; }
__device__ __forceinline__ u64 pk2(float lo, float hi){ u64 r; asm("mov.b64 %0, {%1,%2};" : "=l"(r) : "f"(lo), "f"(hi)); return r; }
__device__ __forceinline__ void up2(u64 v, float& lo, float& hi){ asm("mov.b64 {%0,%1}, %2;" : "=f"(lo), "=f"(hi) : "l"(v)); }
__device__ __forceinline__ u64 ffma2(u64 a, u64 b, u64 c){ u64 d; asm("fma.rn.f32x2 %0, %1, %2, %3;" : "=l"(d) : "l"(a), "l"(b), "l"(c)); return d; }
__device__ __forceinline__ u64 fadd2(u64 a, u64 b){ u64 d; asm("add.rn.f32x2 %0, %1, %2;" : "=l"(d) : "l"(a), "l"(b)); return d; }
__device__ __forceinline__ u64 fmul2(u64 a, u64 b){ u64 d; asm("mul.rn.f32x2 %0, %1, %2;" : "=l"(d) : "l"(a), "l"(b)); return d; }
__device__ __forceinline__ u64 fsub2(u64 a, u64 b){ u64 d; asm("sub.rn.f32x2 %0, %1, %2;" : "=l"(d) : "l"(a), "l"(b)); return d; }

// Exact power-of-2 rescale factor from a stale probe value d (pure ALU).
__device__ __forceinline__ float po2_rescale(float d, int& eacc){
    unsigned u = __float_as_uint(d);
    int e = (int)(u >> 23) & 0xff;
    if (e == 0 || e >= 254) return 1.0f;
    eacc += (e - 127);
    return __uint_as_float((unsigned)(254 - e) << 23);
}

// Exp-domain CRF forward, k-split decomposition:
// 1 CTA = 1 warp = 2 batches; 16 lanes/batch; lane = (4-class group gc) x
// (k-half kh). Each lane computes 4 partial dots over its 16 k's (32 FFMA2
// per warp-step) and combines with its k-partner (lane^8) via shfl+add.
// Per warp-step LSU: 4 LDS.128 + 1 STS.128(pred) + LDG.128 + LDG.32 = 7 ops.
// Numerics: exp-domain, blend-then-po2-rescale every 4 steps, stale pivot.
__global__ __launch_bounds__(32, 8)
void crf_fwd(const float* __restrict__ feats,
             const float* __restrict__ mask,
             const float* __restrict__ trans,
             float* __restrict__ out,
             int seq, int batch)
{
    __shared__ __align__(16) float pbuf[2][2][36];   // [dbl][batch][36]
    const int lane = threadIdx.x & 31;
    const int b    = lane >> 4;       // batch slot (0..1)
    const int g    = lane & 15;
    const int gc   = g & 7;           // class group -> classes 4gc..4gc+3
    const int kh   = g >> 3;          // k-half: k in [16*kh, 16*kh+16)
    const int c0   = gc * 4;
    const int k0   = kh * 16;
    const int batch0 = blockIdx.x * 2;
    int bb = batch0 + b;
    const bool real = (bb < batch);
    if (!real) bb = batch - 1;

    // E2[ci][kp] = (exp T[c0+ci][k0+2kp], exp T[c0+ci][k0+2kp+1])  (32 u64)
    u64 E2[4][8];
#pragma unroll
    for (int ci = 0; ci < 4; ++ci){
        const float* tr = trans + (c0 + ci) * NCLS + k0;
#pragma unroll
        for (int kp = 0; kp < 8; ++kp)
            E2[ci][kp] = pk2(ex2f(tr[2*kp] * LOG2E), ex2f(tr[2*kp+1] * LOG2E));
    }
    u64 ee2[2];
    {
        const float* te = trans + EOSC * NCLS + c0;
        ee2[0] = pk2(ex2f(te[0]*LOG2E), ex2f(te[1]*LOG2E));
        ee2[1] = pk2(ex2f(te[2]*LOG2E), ex2f(te[3]*LOG2E));
    }

    // State: P for this lane's 4 classes (identical across k-partner lanes).
    u64 P2[2];
    P2[0] = pk2((c0+0==SOSC)?1.f:0.f, (c0+1==SOSC)?1.f:0.f);
    P2[1] = pk2((c0+2==SOSC)?1.f:0.f, (c0+3==SOSC)?1.f:0.f);
    int eC = 0;                       // exact integer log2 offset

    const float* fbase = feats + (size_t)bb * NCLS + c0;
    const float* mbase = mask + bb;
    const unsigned fstep = (unsigned)batch * NCLS;
    const unsigned mstep = (unsigned)batch;

    // 8-deep prefetch of exp(feat) (4 classes/lane) and mask.
    u64 fe[8][2]; float mk[8];
#pragma unroll
    for (int j = 0; j < 8; ++j){
        int tc = (j < seq) ? j : (seq - 1);
        float4 f4 = *reinterpret_cast<const float4*>(fbase + (size_t)((unsigned)tc * fstep));
        fe[j][0] = pk2(ex2f(f4.x*LOG2E), ex2f(f4.y*LOG2E));
        fe[j][1] = pk2(ex2f(f4.z*LOG2E), ex2f(f4.w*LOG2E));
        mk[j] = mbase[(unsigned)tc * mstep];
    }

    int t0 = 0;
    for (; t0 + 8 <= seq; t0 += 8){
#pragma unroll
        for (int j = 0; j < 8; ++j){
            // stale rescale pivot: P[class 0] of this batch (lane b*16), ALU+shfl
            float r = 1.0f;
            if ((j & 3) == 0){
                float plo, phi; up2(P2[0], plo, phi);
                float piv = __shfl_sync(0xffffffffu, plo, lane & 16);
                r = po2_rescale(piv, eC);
            }
            // publish P (only kh==0 lanes; partners hold identical copies)
            if (kh == 0){
                ulonglong2 v; v.x = P2[0]; v.y = P2[1];
                *reinterpret_cast<ulonglong2*>(&pbuf[j & 1][b][c0]) = v;
            }
            __syncwarp();
            const float* ld = &pbuf[j & 1][b][k0];
            ulonglong2 v0 = *reinterpret_cast<const ulonglong2*>(ld);
            ulonglong2 v1 = *reinterpret_cast<const ulonglong2*>(ld + 4);
            ulonglong2 v2 = *reinterpret_cast<const ulonglong2*>(ld + 8);
            ulonglong2 v3 = *reinterpret_cast<const ulonglong2*>(ld + 12);
            float s[4];
#pragma unroll
            for (int ci = 0; ci < 4; ++ci){
                u64 aA = 0ull, aB = 0ull;
                aA = ffma2(E2[ci][0], v0.x, aA);
                aB = ffma2(E2[ci][1], v0.y, aB);
                aA = ffma2(E2[ci][2], v1.x, aA);
                aB = ffma2(E2[ci][3], v1.y, aB);
                aA = ffma2(E2[ci][4], v2.x, aA);
                aB = ffma2(E2[ci][5], v2.y, aB);
                aA = ffma2(E2[ci][6], v3.x, aA);
                aB = ffma2(E2[ci][7], v3.y, aB);
                u64 a = fadd2(aA, aB);
                float lo, hi; up2(a, lo, hi);
                s[ci] = lo + hi;                       // partial over this k-half
            }
            // combine with k-partner (lane ^ 8): full 32-k dot
#pragma unroll
            for (int ci = 0; ci < 4; ++ci)
                s[ci] += __shfl_xor_sync(0xffffffffu, s[ci], 8);
            u64 Pn0 = fmul2(pk2(s[0], s[1]), fe[j][0]);
            u64 Pn1 = fmul2(pk2(s[2], s[3]), fe[j][1]);
            // blend first (operands share one scale; exact for mask in {0,1})
            u64 mm = pk2(mk[j], mk[j]);
            P2[0] = ffma2(mm, fsub2(Pn0, P2[0]), P2[0]);
            P2[1] = ffma2(mm, fsub2(Pn1, P2[1]), P2[1]);
            // then uniform po2 rescale of the blended state
            if ((j & 3) == 0){
                u64 rr = pk2(r, r);
                P2[0] = fmul2(P2[0], rr);
                P2[1] = fmul2(P2[1], rr);
            }
            // prefetch step t0+8+j (index clamped BEFORE offset computation)
            {
                int tn = t0 + 8 + j;
                int tc = (tn < seq) ? tn : (seq - 1);
                float4 f4 = *reinterpret_cast<const float4*>(fbase + (size_t)((unsigned)tc * fstep));
                fe[j][0] = pk2(ex2f(f4.x*LOG2E), ex2f(f4.y*LOG2E));
                fe[j][1] = pk2(ex2f(f4.z*LOG2E), ex2f(f4.w*LOG2E));
                mk[j] = mbase[(unsigned)tc * mstep];
            }
        }
    }
    // tail (seq % 8 != 0; not hit for seq=512)
    for (int t = t0; t < seq; ++t){
        if (kh == 0){
            ulonglong2 v; v.x = P2[0]; v.y = P2[1];
            *reinterpret_cast<ulonglong2*>(&pbuf[t & 1][b][c0]) = v;
        }
        __syncwarp();
        const float* ld = &pbuf[t & 1][b][k0];
        ulonglong2 v0 = *reinterpret_cast<const ulonglong2*>(ld);
        ulonglong2 v1 = *reinterpret_cast<const ulonglong2*>(ld + 4);
        ulonglong2 v2 = *reinterpret_cast<const ulonglong2*>(ld + 8);
        ulonglong2 v3 = *reinterpret_cast<const ulonglong2*>(ld + 12);
        float s[4];
#pragma unroll
        for (int ci = 0; ci < 4; ++ci){
            u64 aA = 0ull, aB = 0ull;
            aA = ffma2(E2[ci][0], v0.x, aA);
            aB = ffma2(E2[ci][1], v0.y, aB);
            aA = ffma2(E2[ci][2], v1.x, aA);
            aB = ffma2(E2[ci][3], v1.y, aB);
            aA = ffma2(E2[ci][4], v2.x, aA);
            aB = ffma2(E2[ci][5], v2.y, aB);
            aA = ffma2(E2[ci][6], v3.x, aA);
            aB = ffma2(E2[ci][7], v3.y, aB);
            u64 a = fadd2(aA, aB);
            float lo, hi; up2(a, lo, hi);
            s[ci] = lo + hi;
        }
#pragma unroll
        for (int ci = 0; ci < 4; ++ci)
            s[ci] += __shfl_xor_sync(0xffffffffu, s[ci], 8);
        float4 f4 = *reinterpret_cast<const float4*>(fbase + (size_t)((unsigned)t * fstep));
        u64 Pn0 = fmul2(pk2(s[0], s[1]), pk2(ex2f(f4.x*LOG2E), ex2f(f4.y*LOG2E)));
        u64 Pn1 = fmul2(pk2(s[2], s[3]), pk2(ex2f(f4.z*LOG2E), ex2f(f4.w*LOG2E)));
        float m = mbase[(unsigned)t * mstep];
        u64 mm = pk2(m, m);
        P2[0] = ffma2(mm, fsub2(Pn0, P2[0]), P2[0]);
        P2[1] = ffma2(mm, fsub2(Pn1, P2[1]), P2[1]);
        {   // rescale every tail step
            float plo, phi; up2(P2[0], plo, phi);
            float piv = __shfl_sync(0xffffffffu, plo, lane & 16);
            float r = po2_rescale(piv, eC);
            u64 rr = pk2(r, r);
            P2[0] = fmul2(P2[0], rr);
            P2[1] = fmul2(P2[1], rr);
        }
    }

    // Epilogue: out[b] = ln2 * (eC + log2( sum_c P[c] * exp(T[EOS,c]) ))
    u64 w2 = fmul2(P2[0], ee2[0]);
    w2 = ffma2(P2[1], ee2[1], w2);
    float lo, hi; up2(w2, lo, hi);
    float v = lo + hi;                 // sum over this lane's 4 classes
    // reduce over the 8 class groups (values identical across k-partners)
    v += __shfl_xor_sync(0xffffffffu, v, 1);
    v += __shfl_xor_sync(0xffffffffu, v, 2);
    v += __shfl_xor_sync(0xffffffffu, v, 4);
    if (g == 0 && real)
        out[bb] = ((float)eC + lg2f_(v)) * LN2F;
}

extern "C" void kernel_launch(void* const* d_in, const int* in_sizes, int n_in,
                              void* d_out, int out_size)
{
    const float* feats = (const float*)d_in[0];
    const float* mask  = (const float*)d_in[1];
    const float* trans = (const float*)d_in[2];
    float* out = (float*)d_out;

    const int batch = out_size;                 // out is (batch,)
    const int seq   = in_sizes[1] / batch;      // mask is (seq, batch)

    const int blocks = (batch + 1) / 2;         // 1 warp = 2 batches
    crf_fwd<<<blocks, 32>>>(feats, mask, trans, out, seq, batch);
}

// round 9
// speedup vs baseline: 1.8586x; 1.1445x over previous
#include <cuda_runtime.h>

#define NCLS 32
#define SOSC 30
#define EOSC 31
#define LOG2E 1.4426950408889634f
#define LN2F  0.6931471805599453f

typedef unsigned long long u64;

__device__ __forceinline__ float ex2f(float x){ float r; asm("ex2.approx.f32 %0, %1;" : "=f"(r) : "f"(x)); return r; }
__device__ __forceinline__ float lg2f_(float x){ float r; asm("lg2.approx.f32 %0, %1;" : "=f"(r) : "f"(x)); return r; }
__device__ __forceinline__ u64 pk2(float lo, float hi){ u64 r; asm("mov.b64 %0, {%1,%2};" : "=l"(r) : "f"(lo), "f"(hi)); return r; }
__device__ __forceinline__ void up2(u64 v, float& lo, float& hi){ asm("mov.b64 {%0,%1}, %2;" : "=f"(lo), "=f"(hi) : "l"(v)); }
__device__ __forceinline__ u64 ffma2(u64 a, u64 b, u64 c){ u64 d; asm("fma.rn.f32x2 %0, %1, %2, %3;" : "=l"(d) : "l"(a), "l"(b), "l"(c)); return d; }
__device__ __forceinline__ u64 fadd2(u64 a, u64 b){ u64 d; asm("add.rn.f32x2 %0, %1, %2;" : "=l"(d) : "l"(a), "l"(b)); return d; }
__device__ __forceinline__ u64 fmul2(u64 a, u64 b){ u64 d; asm("mul.rn.f32x2 %0, %1, %2;" : "=l"(d) : "l"(a), "l"(b)); return d; }
__device__ __forceinline__ u64 fsub2(u64 a, u64 b){ u64 d; asm("sub.rn.f32x2 %0, %1, %2;" : "=l"(d) : "l"(a), "l"(b)); return d; }

// 64-bit shuffle via two 32-bit shfl.idx (independent, pipeline fully).
__device__ __forceinline__ u64 shfl64(u64 v, int src){
    float lo, hi; up2(v, lo, hi);
    lo = __shfl_sync(0xffffffffu, lo, src);
    hi = __shfl_sync(0xffffffffu, hi, src);
    return pk2(lo, hi);
}

// Exact power-of-2 rescale factor from a stale probe value d (pure ALU).
__device__ __forceinline__ float po2_rescale(float d, int& eacc){
    unsigned u = __float_as_uint(d);
    int e = (int)(u >> 23) & 0xff;
    if (e == 0 || e >= 254) return 1.0f;
    eacc += (e - 127);
    return __uint_as_float((unsigned)(254 - e) << 23);
}

// Exp-domain CRF forward, k-split + ALL-REGISTER exchange (no smem in loop):
// 1 warp = 2 batches; 16 lanes/batch; lane = (4-class group gc) x (k-half kh).
// P exchange: 16 independent SHFL.32 gather the lane's 16 k-values from the
// 4 lanes that own them (replaces STS + warpsync + 4 LDS: ~88 -> ~40 cyc).
// Numerics: exp-domain, blend-then-po2-rescale every 4 steps, stale pivot.
__global__ __launch_bounds__(32, 8)
void crf_fwd(const float* __restrict__ feats,
             const float* __restrict__ mask,
             const float* __restrict__ trans,
             float* __restrict__ out,
             int seq, int batch)
{
    const int lane = threadIdx.x & 31;
    const int b    = lane >> 4;       // batch slot (0..1)
    const int g    = lane & 15;
    const int gc   = g & 7;           // class group -> classes 4gc..4gc+3
    const int kh   = g >> 3;          // k-half: k in [16*kh, 16*kh+16)
    const int c0   = gc * 4;
    const int k0   = kh * 16;
    const int batch0 = blockIdx.x * 2;
    int bb = batch0 + b;
    const bool real = (bb < batch);
    if (!real) bb = batch - 1;
    // exchange source base: lane holding class quad (4*kh + qi) of this batch
    const int xbase = (lane & 16) | (kh << 2);

    // E2[ci][kp] = (exp T[c0+ci][k0+2kp], exp T[c0+ci][k0+2kp+1])  (32 u64)
    u64 E2[4][8];
#pragma unroll
    for (int ci = 0; ci < 4; ++ci){
        const float* tr = trans + (c0 + ci) * NCLS + k0;
#pragma unroll
        for (int kp = 0; kp < 8; ++kp)
            E2[ci][kp] = pk2(ex2f(tr[2*kp] * LOG2E), ex2f(tr[2*kp+1] * LOG2E));
    }
    u64 ee2[2];
    {
        const float* te = trans + EOSC * NCLS + c0;
        ee2[0] = pk2(ex2f(te[0]*LOG2E), ex2f(te[1]*LOG2E));
        ee2[1] = pk2(ex2f(te[2]*LOG2E), ex2f(te[3]*LOG2E));
    }

    // State: P for this lane's 4 classes (identical across k-partner lanes).
    u64 P2[2];
    P2[0] = pk2((c0+0==SOSC)?1.f:0.f, (c0+1==SOSC)?1.f:0.f);
    P2[1] = pk2((c0+2==SOSC)?1.f:0.f, (c0+3==SOSC)?1.f:0.f);
    int eC = 0;                       // exact integer log2 offset

    const float* fbase = feats + (size_t)bb * NCLS + c0;
    const float* mbase = mask + bb;
    const unsigned fstep = (unsigned)batch * NCLS;
    const unsigned mstep = (unsigned)batch;

    // 8-deep prefetch of exp(feat) (4 classes/lane) and pre-packed mask.
    u64 fe[8][2], mm[8];
#pragma unroll
    for (int j = 0; j < 8; ++j){
        int tc = (j < seq) ? j : (seq - 1);
        float4 f4 = *reinterpret_cast<const float4*>(fbase + (size_t)((unsigned)tc * fstep));
        fe[j][0] = pk2(ex2f(f4.x*LOG2E), ex2f(f4.y*LOG2E));
        fe[j][1] = pk2(ex2f(f4.z*LOG2E), ex2f(f4.w*LOG2E));
        float m = mbase[(unsigned)tc * mstep];
        mm[j] = pk2(m, m);
    }

    int t0 = 0;
    for (; t0 + 8 <= seq; t0 += 8){
#pragma unroll
        for (int j = 0; j < 8; ++j){
            // stale rescale pivot: P[class 0] of this batch (lane b*16), ALU+shfl
            float r = 1.0f;
            if ((j & 3) == 0){
                float plo, phi; up2(P2[0], plo, phi);
                float piv = __shfl_sync(0xffffffffu, plo, lane & 16);
                r = po2_rescale(piv, eC);
            }
            // all-register exchange: gather this lane's 16 k-values (8 u64)
            u64 q[8];
#pragma unroll
            for (int qi = 0; qi < 4; ++qi){
                q[2*qi]   = shfl64(P2[0], xbase + qi);
                q[2*qi+1] = shfl64(P2[1], xbase + qi);
            }
            float s[4];
#pragma unroll
            for (int ci = 0; ci < 4; ++ci){
                u64 aA = 0ull, aB = 0ull;
                aA = ffma2(E2[ci][0], q[0], aA);
                aB = ffma2(E2[ci][1], q[1], aB);
                aA = ffma2(E2[ci][2], q[2], aA);
                aB = ffma2(E2[ci][3], q[3], aB);
                aA = ffma2(E2[ci][4], q[4], aA);
                aB = ffma2(E2[ci][5], q[5], aB);
                aA = ffma2(E2[ci][6], q[6], aA);
                aB = ffma2(E2[ci][7], q[7], aB);
                u64 a = fadd2(aA, aB);
                float lo, hi; up2(a, lo, hi);
                s[ci] = lo + hi;                       // partial over this k-half
            }
            // combine with k-partner (lane ^ 8): full 32-k dot
#pragma unroll
            for (int ci = 0; ci < 4; ++ci)
                s[ci] += __shfl_xor_sync(0xffffffffu, s[ci], 8);
            u64 Pn0 = fmul2(pk2(s[0], s[1]), fe[j][0]);
            u64 Pn1 = fmul2(pk2(s[2], s[3]), fe[j][1]);
            // blend first (operands share one scale; exact for mask in {0,1})
            P2[0] = ffma2(mm[j], fsub2(Pn0, P2[0]), P2[0]);
            P2[1] = ffma2(mm[j], fsub2(Pn1, P2[1]), P2[1]);
            // then uniform po2 rescale of the blended state
            if ((j & 3) == 0){
                u64 rr = pk2(r, r);
                P2[0] = fmul2(P2[0], rr);
                P2[1] = fmul2(P2[1], rr);
            }
            // prefetch step t0+8+j (index clamped BEFORE offset computation)
            {
                int tn = t0 + 8 + j;
                int tc = (tn < seq) ? tn : (seq - 1);
                float4 f4 = *reinterpret_cast<const float4*>(fbase + (size_t)((unsigned)tc * fstep));
                fe[j][0] = pk2(ex2f(f4.x*LOG2E), ex2f(f4.y*LOG2E));
                fe[j][1] = pk2(ex2f(f4.z*LOG2E), ex2f(f4.w*LOG2E));
                float m = mbase[(unsigned)tc * mstep];
                mm[j] = pk2(m, m);
            }
        }
    }
    // tail (seq % 8 != 0; not hit for seq=512)
    for (int t = t0; t < seq; ++t){
        u64 q[8];
#pragma unroll
        for (int qi = 0; qi < 4; ++qi){
            q[2*qi]   = shfl64(P2[0], xbase + qi);
            q[2*qi+1] = shfl64(P2[1], xbase + qi);
        }
        float s[4];
#pragma unroll
        for (int ci = 0; ci < 4; ++ci){
            u64 aA = 0ull, aB = 0ull;
#pragma unroll
            for (int kp = 0; kp < 8; kp += 2){
                aA = ffma2(E2[ci][kp],   q[kp],   aA);
                aB = ffma2(E2[ci][kp+1], q[kp+1], aB);
            }
            u64 a = fadd2(aA, aB);
            float lo, hi; up2(a, lo, hi);
            s[ci] = lo + hi;
        }
#pragma unroll
        for (int ci = 0; ci < 4; ++ci)
            s[ci] += __shfl_xor_sync(0xffffffffu, s[ci], 8);
        float4 f4 = *reinterpret_cast<const float4*>(fbase + (size_t)((unsigned)t * fstep));
        u64 Pn0 = fmul2(pk2(s[0], s[1]), pk2(ex2f(f4.x*LOG2E), ex2f(f4.y*LOG2E)));
        u64 Pn1 = fmul2(pk2(s[2], s[3]), pk2(ex2f(f4.z*LOG2E), ex2f(f4.w*LOG2E)));
        float m = mbase[(unsigned)t * mstep];
        u64 mv = pk2(m, m);
        P2[0] = ffma2(mv, fsub2(Pn0, P2[0]), P2[0]);
        P2[1] = ffma2(mv, fsub2(Pn1, P2[1]), P2[1]);
        {   // rescale every tail step
            float plo, phi; up2(P2[0], plo, phi);
            float piv = __shfl_sync(0xffffffffu, plo, lane & 16);
            float r = po2_rescale(piv, eC);
            u64 rr = pk2(r, r);
            P2[0] = fmul2(P2[0], rr);
            P2[1] = fmul2(P2[1], rr);
        }
    }

    // Epilogue: out[b] = ln2 * (eC + log2( sum_c P[c] * exp(T[EOS,c]) ))
    u64 w2 = fmul2(P2[0], ee2[0]);
    w2 = ffma2(P2[1], ee2[1], w2);
    float lo, hi; up2(w2, lo, hi);
    float v = lo + hi;                 // sum over this lane's 4 classes
    // reduce over the 8 class groups (values identical across k-partners)
    v += __shfl_xor_sync(0xffffffffu, v, 1);
    v += __shfl_xor_sync(0xffffffffu, v, 2);
    v += __shfl_xor_sync(0xffffffffu, v, 4);
    if (g == 0 && real)
        out[bb] = ((float)eC + lg2f_(v)) * LN2F;
}

extern "C" void kernel_launch(void* const* d_in, const int* in_sizes, int n_in,
                              void* d_out, int out_size)
{
    const float* feats = (const float*)d_in[0];
    const float* mask  = (const float*)d_in[1];
    const float* trans = (const float*)d_in[2];
    float* out = (float*)d_out;

    const int batch = out_size;                 // out is (batch,)
    const int seq   = in_sizes[1] / batch;      // mask is (seq, batch)

    const int blocks = (batch + 1) / 2;         // 1 warp = 2 batches
    crf_fwd<<<blocks, 32>>>(feats, mask, trans, out, seq, batch);
}